// round 16
// baseline (speedup 1.0000x reference)
#include <cuda_runtime.h>
#include <cstdint>

// upfirdn2d, UP=1, DOWN=2, PAD=5, separable sym6 (12 taps), fp32.
// v14: intra-thread software pipeline. Per 16-output-row chunk c:
//   1. issue chunk c's 26 vertical input loads (independent LDG -> regs)
//   2. horizontal pass for chunk c-1 from s_tmp[(c-1)&1]  (runs in LDG shadow)
//   3. vertical taps for chunk c -> s_tmp[c&1]
//   4. __syncthreads()
// All 512 threads both load and compute; double-buffered tmp = 1 barrier/chunk.

#define IMG_H   256
#define IMG_W   256
#define OUT_H   128
#define OUT_W   128
#define NT      512
#define NCHK    4             // chunks per CTA (16 out rows each)
#define TSTRIDE 276           // 276 % 32 = 20
#define PADL    8             // data words [8, 264)
#define TBUF    (16 * TSTRIDE)

#define HR0  ( 0.015404109327027373f)
#define HR1  ( 0.0034907120842174702f)
#define HR2  (-0.11799011114819057f)
#define HR3  (-0.048311742585633f)
#define HR4  ( 0.4910559419267466f)
#define HR5  ( 0.787641141030194f)
#define HR6  ( 0.3379294217276218f)
#define HR7  (-0.07263752278646252f)
#define HR8  (-0.021060292512300564f)
#define HR9  ( 0.04472490177066578f)
#define HR10 ( 0.0017677118642428036f)
#define HR11 (-0.007800708325034148f)

__device__ __forceinline__ float tap12(const float* w) {
    float a;
    a = HR0 * w[0];
    a = fmaf(HR1,  w[1],  a);
    a = fmaf(HR2,  w[2],  a);
    a = fmaf(HR3,  w[3],  a);
    a = fmaf(HR4,  w[4],  a);
    a = fmaf(HR5,  w[5],  a);
    a = fmaf(HR6,  w[6],  a);
    a = fmaf(HR7,  w[7],  a);
    a = fmaf(HR8,  w[8],  a);
    a = fmaf(HR9,  w[9],  a);
    a = fmaf(HR10, w[10], a);
    a = fmaf(HR11, w[11], a);
    return a;
}

// Horizontal: 4 outputs (cols 4g..4g+3) from a 24-word window.
__device__ __forceinline__ void hquad(const float* __restrict__ rowv,
                                      float* __restrict__ dst)
{
    float v[24];
    #pragma unroll
    for (int m = 0; m < 6; m++) {
        float4 q = *reinterpret_cast<const float4*>(rowv + 4 * m);
        v[4*m+0] = q.x; v[4*m+1] = q.y; v[4*m+2] = q.z; v[4*m+3] = q.w;
    }
    float4 o;
    o.x = tap12(&v[3]);
    o.y = tap12(&v[5]);
    o.z = tap12(&v[7]);
    o.w = tap12(&v[9]);
    *reinterpret_cast<float4*>(dst) = o;
}

// Load chunk c's 26 input rows of one column into w[] (independent LDGs).
template<bool CHECK>
__device__ __forceinline__ void vload26(const float* __restrict__ colp,
                                        float* __restrict__ w, int g0)
{
    #pragma unroll
    for (int t = 0; t < 26; t++) {
        int g = g0 + t;
        if (CHECK && (unsigned)g >= (unsigned)IMG_H) w[t] = 0.0f;
        else                                         w[t] = __ldg(colp + g * IMG_W);
    }
}

__global__ void __launch_bounds__(NT, 2)
hp_sym6_v14(const float* __restrict__ in, float* __restrict__ out)
{
    __shared__ float s_tmp[2 * TBUF];          // 35328 B

    const int ty  = blockIdx.x;                // tile (fastest -> L2 halo reuse)
    const int img = blockIdx.y;
    const int tid = threadIdx.x;
    const int i0  = ty * 64;

    const float* __restrict__ src    = in  + (size_t)img * (IMG_H * IMG_W);
    float*       __restrict__ dstimg = out + (size_t)img * (OUT_H * OUT_W);

    // zero tmp pad words [0,8) and [264,276) of both buffers
    for (int z = tid; z < 2 * 16 * 20; z += NT) {
        int b  = z / 320;
        int zz = z - b * 320;
        int rr = zz / 20;
        int pz = zz - rr * 20;
        s_tmp[b * TBUF + rr * TSTRIDE + (pz < 8 ? pz : 256 + pz)] = 0.0f;
    }
    __syncthreads();

    // V mapping: (column, half): half vh -> chunk rows 8vh..8vh+7
    const int vcol = tid & 255;
    const int vh   = tid >> 8;
    const float* colp = src + vcol;

    // H mapping: (row in chunk 0..15, group of 4 output cols)
    const int hrow = tid >> 5;
    const int hg   = tid & 31;

    float w[26];

    #pragma unroll
    for (int c = 0; c < NCHK; c++) {
        // ---- 1. issue chunk c's vertical loads (in-flight through step 2) ----
        const int g0 = 2 * (i0 + 16 * c + 8 * vh) - 5;
        if (g0 >= 0 && g0 + 25 < IMG_H) vload26<false>(colp, w, g0);
        else                            vload26<true >(colp, w, g0);

        // ---- 2. horizontal for chunk c-1 (smem + FMA; hides LDG latency) ----
        if (c > 0) {
            const float* rowv = s_tmp + ((c - 1) & 1) * TBUF
                              + hrow * TSTRIDE + 8 * hg;
            hquad(rowv, dstimg + (i0 + 16 * (c - 1) + hrow) * OUT_W + 4 * hg);
        }

        // ---- 3. vertical taps for chunk c -> s_tmp[c&1] ----
        {
            float* sdst = s_tmp + (c & 1) * TBUF + (8 * vh) * TSTRIDE + PADL + vcol;
            #pragma unroll
            for (int m = 0; m < 8; m++)
                sdst[m * TSTRIDE] = tap12(&w[2 * m]);
        }
        __syncthreads();
    }

    // final H for chunk NCHK-1 (buffer (NCHK-1)&1, ordered by last barrier)
    {
        const float* rowv = s_tmp + ((NCHK - 1) & 1) * TBUF
                          + hrow * TSTRIDE + 8 * hg;
        hquad(rowv, dstimg + (i0 + 16 * (NCHK - 1) + hrow) * OUT_W + 4 * hg);
    }
}

extern "C" void kernel_launch(void* const* d_in, const int* in_sizes, int n_in,
                              void* d_out, int out_size)
{
    const float* x = (const float*)d_in[0];
    float* y = (float*)d_out;

    int n_img = in_sizes[0] / (IMG_H * IMG_W);   // 1024
    dim3 grid(OUT_H / 64, n_img);                // (2, 1024)
    hp_sym6_v14<<<grid, NT>>>(x, y);
}

// round 17
// speedup vs baseline: 1.1668x; 1.1668x over previous
#include <cuda_runtime.h>
#include <cstdint>

// upfirdn2d, UP=1, DOWN=2, PAD=5, separable sym6 (12 taps), fp32.
// v15: fully fused streaming kernel. Each lane owns one column PAIR:
// vertical 12-tap via float2 register ring (rolling loads), then the
// horizontal 12-tap window (12 cols = own pair +/-3 lanes) is gathered with
// 10 warp shuffles and the output stored directly. Warps overlap by 6 pairs
// (26 outputs/warp) so there is NO smem and NO __syncthreads anywhere:
// loads stream continuously for the whole kernel (v3's DRAM-friendly shape
// without its serialized horizontal tail).

#define IMG_H   256
#define IMG_W   256
#define OUT_H   128
#define OUT_W   128
#define NT      320           // 10 warps: 2 strips x 5 warps
#define FULLM   0xffffffffu

#define HR0  ( 0.015404109327027373f)
#define HR1  ( 0.0034907120842174702f)
#define HR2  (-0.11799011114819057f)
#define HR3  (-0.048311742585633f)
#define HR4  ( 0.4910559419267466f)
#define HR5  ( 0.787641141030194f)
#define HR6  ( 0.3379294217276218f)
#define HR7  (-0.07263752278646252f)
#define HR8  (-0.021060292512300564f)
#define HR9  ( 0.04472490177066578f)
#define HR10 ( 0.0017677118642428036f)
#define HR11 (-0.007800708325034148f)

__device__ __forceinline__ float2 tap12v(const float2* w) {
    float2 a;
    a.x = HR0 * w[0].x;            a.y = HR0 * w[0].y;
    a.x = fmaf(HR1,  w[1].x, a.x); a.y = fmaf(HR1,  w[1].y, a.y);
    a.x = fmaf(HR2,  w[2].x, a.x); a.y = fmaf(HR2,  w[2].y, a.y);
    a.x = fmaf(HR3,  w[3].x, a.x); a.y = fmaf(HR3,  w[3].y, a.y);
    a.x = fmaf(HR4,  w[4].x, a.x); a.y = fmaf(HR4,  w[4].y, a.y);
    a.x = fmaf(HR5,  w[5].x, a.x); a.y = fmaf(HR5,  w[5].y, a.y);
    a.x = fmaf(HR6,  w[6].x, a.x); a.y = fmaf(HR6,  w[6].y, a.y);
    a.x = fmaf(HR7,  w[7].x, a.x); a.y = fmaf(HR7,  w[7].y, a.y);
    a.x = fmaf(HR8,  w[8].x, a.x); a.y = fmaf(HR8,  w[8].y, a.y);
    a.x = fmaf(HR9,  w[9].x, a.x); a.y = fmaf(HR9,  w[9].y, a.y);
    a.x = fmaf(HR10, w[10].x, a.x); a.y = fmaf(HR10, w[10].y, a.y);
    a.x = fmaf(HR11, w[11].x, a.x); a.y = fmaf(HR11, w[11].y, a.y);
    return a;
}

// One 16-output-row strip. Lane owns tmp pair p (cols 2p, 2p+1); its output
// column j == p. Horizontal window: y[j] = sum_k HR[k]*tmp[2j+k-5] =
//   HR0*hi(p-3) + HR1..2*(p-2) + HR3..4*(p-1) + HR5..6*(p) + HR7..8*(p+1)
//   + HR9..10*(p+2) + HR11*lo(p+3)        (pairs gathered via shfl +/-3)
template<bool CHECK>
__device__ __forceinline__ void strip16(const float2* __restrict__ colp,
                                        float pmask, int g0,
                                        float* __restrict__ dst, bool jvalid)
{
    float2 w[12];
    #pragma unroll
    for (int t = 0; t < 10; t++) {
        int g = g0 + t;
        if (CHECK && (unsigned)g >= (unsigned)IMG_H) w[t] = make_float2(0.f, 0.f);
        else                                         w[t] = __ldg(colp + g * (IMG_W / 2));
    }
    #pragma unroll
    for (int i = 0; i < 16; i++) {
        int gA = g0 + 2 * i + 10;
        int gB = gA + 1;
        if (CHECK && (unsigned)gA >= (unsigned)IMG_H) w[10] = make_float2(0.f, 0.f);
        else                                          w[10] = __ldg(colp + gA * (IMG_W / 2));
        if (CHECK && (unsigned)gB >= (unsigned)IMG_H) w[11] = make_float2(0.f, 0.f);
        else                                          w[11] = __ldg(colp + gB * (IMG_W / 2));

        float2 t = tap12v(w);
        t.x *= pmask;                    // zero out-of-image column pairs
        t.y *= pmask;                    // (must happen BEFORE shuffles)

        float um3y = __shfl_up_sync(FULLM, t.y, 3);
        float um2x = __shfl_up_sync(FULLM, t.x, 2);
        float um2y = __shfl_up_sync(FULLM, t.y, 2);
        float um1x = __shfl_up_sync(FULLM, t.x, 1);
        float um1y = __shfl_up_sync(FULLM, t.y, 1);
        float dp1x = __shfl_down_sync(FULLM, t.x, 1);
        float dp1y = __shfl_down_sync(FULLM, t.y, 1);
        float dp2x = __shfl_down_sync(FULLM, t.x, 2);
        float dp2y = __shfl_down_sync(FULLM, t.y, 2);
        float dp3x = __shfl_down_sync(FULLM, t.x, 3);

        float y;
        y = HR0 * um3y;
        y = fmaf(HR1,  um2x, y);
        y = fmaf(HR2,  um2y, y);
        y = fmaf(HR3,  um1x, y);
        y = fmaf(HR4,  um1y, y);
        y = fmaf(HR5,  t.x,  y);
        y = fmaf(HR6,  t.y,  y);
        y = fmaf(HR7,  dp1x, y);
        y = fmaf(HR8,  dp1y, y);
        y = fmaf(HR9,  dp2x, y);
        y = fmaf(HR10, dp2y, y);
        y = fmaf(HR11, dp3x, y);

        if (jvalid) dst[i * OUT_W] = y;

        #pragma unroll
        for (int k = 0; k < 10; k++) w[k] = w[k + 2];
    }
}

__global__ void __launch_bounds__(NT, 3)
hp_sym6_v15(const float* __restrict__ in, float* __restrict__ out)
{
    const int tile = blockIdx.x;             // 0..3 (fastest -> L2 halo reuse)
    const int img  = blockIdx.y;
    const int tid  = threadIdx.x;
    const int wid  = tid >> 5;               // 0..9
    const int lane = tid & 31;

    const int s = (wid >= 5) ? 1 : 0;        // strip within tile (16 rows)
    const int w = wid - 5 * s;               // 0..4 (warp within strip)

    const int p  = 26 * w + lane - 3;        // owned column pair (may be OOB)
    const int pc = p < 0 ? 0 : (p > 127 ? 127 : p);   // clamped for safe loads
    const float pmask  = ((unsigned)p < 128u) ? 1.0f : 0.0f;
    const bool  jvalid = (lane >= 3) && (lane <= 28) && (p < 128);

    const int i0 = tile * 32 + s * 16;       // first output row of strip
    const int g0 = 2 * i0 - 5;               // first input row (42-row window)

    const float* __restrict__ src = in + (size_t)img * (IMG_H * IMG_W);
    const float2* colp = reinterpret_cast<const float2*>(src) + pc;
    float* __restrict__ dst =
        out + (size_t)img * (OUT_H * OUT_W) + i0 * OUT_W + p;

    if (g0 >= 0 && g0 + 41 < IMG_H) strip16<false>(colp, pmask, g0, dst, jvalid);
    else                            strip16<true >(colp, pmask, g0, dst, jvalid);
}

extern "C" void kernel_launch(void* const* d_in, const int* in_sizes, int n_in,
                              void* d_out, int out_size)
{
    const float* x = (const float*)d_in[0];
    float* y = (float*)d_out;

    int n_img = in_sizes[0] / (IMG_H * IMG_W);   // 1024
    dim3 grid(OUT_H / 32, n_img);                // (4, 1024)
    hp_sym6_v15<<<grid, NT>>>(x, y);
}